// round 8
// baseline (speedup 1.0000x reference)
#include <cuda_runtime.h>
#include <math.h>

#define N    2048
#define K    128
#define NMAX 40

#define SQL2E 1.2011224087864498f   // sqrt(log2(e))
#define NL2E  -0.7213475204444817f  // -0.5*log2(e)
#define HL2E  0.7213475204444817f   // 0.5*log2(e)

typedef unsigned long long ull;

__device__ float g_u  [N * K];      // standardized * sqrt(log2 e)
__device__ float g_xs [N * K];      // standardized
__device__ float g_rh [N];          // 0.5*log2(e)*||xs_i||^2
__device__ float g_S  [N];          // joint sums
__device__ float g_T  [NMAX * K];   // scaled moments
__device__ float g_pS [64 * K];     // partial column sums
__device__ float g_pQ [64 * K];     // partial column sumsq
__device__ float g_acc;             // final sum of v_i
__device__ unsigned g_cnt;          // combine-block arrival counter

__device__ __forceinline__ float ex2f(float x) {
    float r; asm("ex2.approx.f32 %0, %1;" : "=f"(r) : "f"(x)); return r;
}
__device__ __forceinline__ float lg2f(float x) {
    float r; asm("lg2.approx.f32 %0, %1;" : "=f"(r) : "f"(x)); return r;
}
#define LN2f 0.6931471805599453f
__device__ __forceinline__ float lnf(float x) { return lg2f(x) * LN2f; }

__device__ __forceinline__ ull splat2(float x) {
    ull r; asm("mov.b64 %0, {%1, %1};" : "=l"(r) : "f"(x)); return r;
}
__device__ __forceinline__ ull pack2(float lo, float hi) {
    ull r; asm("mov.b64 %0, {%1, %2};" : "=l"(r) : "f"(lo), "f"(hi)); return r;
}
__device__ __forceinline__ ull fma2(ull a, ull b, ull c) {
    ull d; asm("fma.rn.f32x2 %0, %1, %2, %3;" : "=l"(d) : "l"(a), "l"(b), "l"(c)); return d;
}
__device__ __forceinline__ void unpack2(ull v, float& lo, float& hi) {
    asm("mov.b64 {%0, %1}, %2;" : "=f"(lo), "=f"(hi) : "l"(v));
}

// ---------------------------------------------------------------------------
// K1: partial column sums (coalesced) + zero accumulators. 64 blocks x 128.
// ---------------------------------------------------------------------------
__global__ __launch_bounds__(128) void sums_kernel(const float* __restrict__ z) {
    const int k = threadIdx.x;
    const int b = blockIdx.x;
    const int r0 = b * 32;
    float s = 0.f, sq = 0.f;
#pragma unroll 8
    for (int r = 0; r < 32; r++) {
        float v = z[(r0 + r) * K + k];
        s += v; sq += v * v;
    }
    g_pS[b * K + k] = s;
    g_pQ[b * K + k] = sq;

    if (b < NMAX)               g_T[b * 128 + k] = 0.f;           // 40*128
    else if (b < NMAX + 16)     g_S[(b - NMAX) * 128 + k] = 0.f;  // 16*128
    if (b == 0 && k == 0) { g_acc = 0.f; g_cnt = 0u; }
}

// ---------------------------------------------------------------------------
// K2: finalize (redundant) + standardize + moments + row norms.
// 256 blocks x 128 threads; block = 8 rows, thread = column k.
// ---------------------------------------------------------------------------
__global__ __launch_bounds__(128) void standmom_kernel(const float* __restrict__ z) {
    const int k = threadIdx.x;
    const int r0 = blockIdx.x * 8;

    float s = 0.f, sq = 0.f;
#pragma unroll 8
    for (int b = 0; b < 64; b++) {
        s  += g_pS[b * K + k];
        sq += g_pQ[b * K + k];
    }
    const float mean = s / (float)N;
    float var = (sq - s * mean) / (float)(N - 1);
    var = fmaxf(var, 0.f);
    const float rs = 1.f / (sqrtf(var) + 1e-6f);

    float bx[8], q[8], rh8[8];
#pragma unroll
    for (int r = 0; r < 8; r++) {
        int row = r0 + r;
        float xs = (z[row * K + k] - mean) * rs;
        g_xs[row * K + k] = xs;
        g_u [row * K + k] = xs * SQL2E;
        bx[r] = xs;
        q[r]  = ex2f(NL2E * xs * xs);
        rh8[r] = xs * xs;
    }

    float acc[NMAX];
#pragma unroll
    for (int n = 0; n < NMAX; n++) acc[n] = 0.f;
#pragma unroll
    for (int n = 0; n < NMAX; n++) {
        const float rinv = 1.0f / (float)(n + 1);
#pragma unroll
        for (int r = 0; r < 8; r++) {
            acc[n] += q[r];
            q[r] *= bx[r] * rinv;
        }
    }
#pragma unroll
    for (int n = 0; n < NMAX; n++) atomicAdd(&g_T[n * K + k], acc[n]);

#pragma unroll
    for (int o = 16; o; o >>= 1)
#pragma unroll
        for (int r = 0; r < 8; r++)
            rh8[r] += __shfl_xor_sync(0xffffffffu, rh8[r], o);

    __shared__ float shr[4][8];
    const int w = k >> 5, lane = k & 31;
    if (lane == 0) {
#pragma unroll
        for (int r = 0; r < 8; r++) shr[w][r] = rh8[r];
    }
    __syncthreads();
    if (k < 8)
        g_rh[r0 + k] = HL2E * (shr[0][k] + shr[1][k] + shr[2][k] + shr[3][k]);
}

// ---------------------------------------------------------------------------
// K3: symmetric Gram (fma.rn.f32x2) + fused exp + row/col sums.
// ---------------------------------------------------------------------------
__global__ __launch_bounds__(256) void gram_kernel() {
    __shared__ float As[32][132];
    __shared__ float Bs[32][132];
    __shared__ float colP[16][128];

    const int tid = threadIdx.x;
    const int tx = tid & 15, ty = tid >> 4;

    int rem = blockIdx.x, ti = 0;
    for (int t = 0; t < 16; t++) {
        int L = 16 - t;
        if (rem < L) { ti = t; break; }
        rem -= L;
    }
    const int tj = ti + rem;
    const int i0 = ti * 128, j0 = tj * 128;

    ull acc2[8][4];
#pragma unroll
    for (int m = 0; m < 8; m++)
#pragma unroll
        for (int p = 0; p < 4; p++) acc2[m][p] = splat2(0.f);

#pragma unroll 1
    for (int kc = 0; kc < K; kc += 32) {
        __syncthreads();
#pragma unroll
        for (int r = 0; r < 4; r++) {
            int f = tid + 256 * r;
            int row = f >> 3, kp = (f & 7) * 4;
            float4 va = *(const float4*)&g_u[(i0 + row) * K + kc + kp];
            As[kp + 0][row] = va.x; As[kp + 1][row] = va.y;
            As[kp + 2][row] = va.z; As[kp + 3][row] = va.w;
            float4 vb = *(const float4*)&g_u[(j0 + row) * K + kc + kp];
            Bs[kp + 0][row] = vb.x; Bs[kp + 1][row] = vb.y;
            Bs[kp + 2][row] = vb.z; Bs[kp + 3][row] = vb.w;
        }
        __syncthreads();
#pragma unroll
        for (int kk = 0; kk < 32; kk++) {
            float4 a0 = *(const float4*)&As[kk][ty * 8];
            float4 a1 = *(const float4*)&As[kk][ty * 8 + 4];
            float4 b0 = *(const float4*)&Bs[kk][tx * 8];
            float4 b1 = *(const float4*)&Bs[kk][tx * 8 + 4];
            ull av2[8];
            av2[0] = splat2(a0.x); av2[1] = splat2(a0.y);
            av2[2] = splat2(a0.z); av2[3] = splat2(a0.w);
            av2[4] = splat2(a1.x); av2[5] = splat2(a1.y);
            av2[6] = splat2(a1.z); av2[7] = splat2(a1.w);
            ull bv[4];
            bv[0] = pack2(b0.x, b0.y); bv[1] = pack2(b0.z, b0.w);
            bv[2] = pack2(b1.x, b1.y); bv[3] = pack2(b1.z, b1.w);
#pragma unroll
            for (int m = 0; m < 8; m++)
#pragma unroll
                for (int p = 0; p < 4; p++)
                    acc2[m][p] = fma2(av2[m], bv[p], acc2[m][p]);
        }
    }

    float rhi[8], rhj[8];
#pragma unroll
    for (int m = 0; m < 8; m++) rhi[m] = g_rh[i0 + ty * 8 + m];
#pragma unroll
    for (int n = 0; n < 8; n++) rhj[n] = g_rh[j0 + tx * 8 + n];

    float rows[8], cols[8];
#pragma unroll
    for (int m = 0; m < 8; m++) rows[m] = 0.f;
#pragma unroll
    for (int n = 0; n < 8; n++) cols[n] = 0.f;
#pragma unroll
    for (int m = 0; m < 8; m++) {
#pragma unroll
        for (int p = 0; p < 4; p++) {
            float glo, ghi;
            unpack2(acc2[m][p], glo, ghi);
            float e0 = ex2f(glo - rhi[m] - rhj[2 * p + 0]);
            float e1 = ex2f(ghi - rhi[m] - rhj[2 * p + 1]);
            rows[m] += e0 + e1;
            cols[2 * p + 0] += e0;
            cols[2 * p + 1] += e1;
        }
    }

#pragma unroll
    for (int o = 8; o; o >>= 1)
#pragma unroll
        for (int m = 0; m < 8; m++)
            rows[m] += __shfl_xor_sync(0xffffffffu, rows[m], o);
    if (tx == 0) {
#pragma unroll
        for (int m = 0; m < 8; m++)
            atomicAdd(&g_S[i0 + ty * 8 + m], rows[m]);
    }

#pragma unroll
    for (int n = 0; n < 8; n++) colP[ty][tx * 8 + n] = cols[n];
    __syncthreads();
    if (ti != tj && tid < 128) {
        float ssum = 0.f;
#pragma unroll
        for (int t = 0; t < 16; t++) ssum += colP[t][tid];
        atomicAdd(&g_S[j0 + tid], ssum);
    }
}

// ---------------------------------------------------------------------------
// K4: combine + finish. 256 blocks x 512 threads; block = 8 rows.
// Thread: k = tid&127, group g = tid>>7 (2 rows each).
// ---------------------------------------------------------------------------
__global__ __launch_bounds__(512) void combine_kernel(float* __restrict__ out) {
    __shared__ float T_sh[NMAX * K];   // 20 KB
    const int tid = threadIdx.x;
    const int k = tid & 127;
    const int g = tid >> 7;
    const int i0 = blockIdx.x * 8;
    const int r0 = i0 + g * 2;

    // prefetch this thread's xs before the barrier (overlaps T load latency)
    float a0 = g_xs[(r0 + 0) * K + k];
    float a1 = g_xs[(r0 + 1) * K + k];

    // cooperative coalesced load of T (1280 float4 over 512 threads)
#pragma unroll
    for (int r = 0; r < 3; r++) {
        int idx = tid + 512 * r;
        if (idx < (NMAX * K) / 4)
            reinterpret_cast<float4*>(T_sh)[idx] =
                reinterpret_cast<const float4*>(g_T)[idx];
    }
    __syncthreads();

    float S0 = T_sh[(NMAX - 1) * K + k];
    float S1 = S0;
#pragma unroll
    for (int n = NMAX - 2; n >= 0; n--) {
        float t = T_sh[n * K + k];
        S0 = fmaf(S0, a0, t);
        S1 = fmaf(S1, a1, t);
    }

    float v0 = lnf(S0) - 0.5f * a0 * a0;
    float v1 = lnf(S1) - 0.5f * a1 * a1;

#pragma unroll
    for (int o = 16; o; o >>= 1) {
        v0 += __shfl_xor_sync(0xffffffffu, v0, o);
        v1 += __shfl_xor_sync(0xffffffffu, v1, o);
    }

    __shared__ float part[16][2];
    __shared__ float vv[8];
    const int ww = tid >> 5, lane = tid & 31;
    if (lane == 0) { part[ww][0] = v0; part[ww][1] = v1; }
    __syncthreads();
    if (tid < 8) {
        int gg = tid >> 1, rr = tid & 1;
        float tot = part[gg * 4 + 0][rr] + part[gg * 4 + 1][rr]
                  + part[gg * 4 + 2][rr] + part[gg * 4 + 3][rr];
        vv[tid] = logf(g_S[i0 + gg * 2 + rr]) - tot;   // v_i
    }
    __syncthreads();

    if (tid == 0) {
        float bsum = 0.f;
#pragma unroll
        for (int r = 0; r < 8; r++) bsum += vv[r];
        atomicAdd(&g_acc, bsum);
        __threadfence();
        unsigned old = atomicAdd(&g_cnt, 1u);
        if (old == (unsigned)(gridDim.x - 1)) {
            __threadfence();
            out[0] = g_acc / (float)N + (float)(K - 1) * logf((float)N);
        }
    }
}

// ---------------------------------------------------------------------------
extern "C" void kernel_launch(void* const* d_in, const int* in_sizes, int n_in,
                              void* d_out, int out_size) {
    (void)in_sizes; (void)n_in; (void)out_size;
    const float* z = (const float*)d_in[0];
    float* out = (float*)d_out;

    sums_kernel    <<<64, 128>>>(z);
    standmom_kernel<<<256, 128>>>(z);
    gram_kernel    <<<136, 256>>>();
    combine_kernel <<<256, 512>>>(out);
}

// round 9
// speedup vs baseline: 1.0060x; 1.0060x over previous
#include <cuda_runtime.h>
#include <math.h>

#define N    2048
#define K    128
#define NMAX 40
#define NB   136          // grid size; all blocks resident (<= 148 SMs)

#define SQL2E 1.2011224087864498f   // sqrt(log2(e))
#define NL2E  -0.7213475204444817f  // -0.5*log2(e)
#define HL2E  0.7213475204444817f   // 0.5*log2(e)
#define LN2f  0.6931471805599453f

typedef unsigned long long ull;

__device__ float g_u  [N * K];
__device__ float g_xs [N * K];
__device__ float g_rh [N];
__device__ float g_S  [N];
__device__ float g_T  [NMAX * K];
__device__ float g_pS [128 * K];
__device__ float g_pQ [128 * K];
__device__ float g_acc;
__device__ unsigned g_bar[4];      // zero-init; monotonic epoch barriers

__device__ __forceinline__ float ex2f(float x) {
    float r; asm("ex2.approx.f32 %0, %1;" : "=f"(r) : "f"(x)); return r;
}
__device__ __forceinline__ float lg2f(float x) {
    float r; asm("lg2.approx.f32 %0, %1;" : "=f"(r) : "f"(x)); return r;
}
__device__ __forceinline__ float lnf(float x) { return lg2f(x) * LN2f; }

__device__ __forceinline__ ull splat2(float x) {
    ull r; asm("mov.b64 %0, {%1, %1};" : "=l"(r) : "f"(x)); return r;
}
__device__ __forceinline__ ull pack2(float lo, float hi) {
    ull r; asm("mov.b64 %0, {%1, %2};" : "=l"(r) : "f"(lo), "f"(hi)); return r;
}
__device__ __forceinline__ ull fma2(ull a, ull b, ull c) {
    ull d; asm("fma.rn.f32x2 %0, %1, %2, %3;" : "=l"(d) : "l"(a), "l"(b), "l"(c)); return d;
}
__device__ __forceinline__ void unpack2(ull v, float& lo, float& hi) {
    asm("mov.b64 {%0, %1}, %2;" : "=f"(lo), "=f"(hi) : "l"(v));
}

// Grid barrier: monotonic epoch counter, replay-safe, no reset needed.
__device__ __forceinline__ void grid_bar(int b) {
    __threadfence();
    __syncthreads();
    if (threadIdx.x == 0) {
        unsigned ticket = atomicAdd(&g_bar[b], 1u);
        unsigned target = (ticket / NB + 1u) * NB;
        while (*(volatile unsigned*)&g_bar[b] < target) __nanosleep(32);
        __threadfence();
    }
    __syncthreads();
}

__global__ __launch_bounds__(256, 1) void fused_kernel(
        const float* __restrict__ z, float* __restrict__ out) {
    __shared__ __align__(16) char s_buf[42240];
    const int tid = threadIdx.x;
    const int B = blockIdx.x;

    // ======================= P0: partial column sums + zero ================
    if (B < 128) {
        const int k = tid & 127;
        if (tid < 128) {
            const int r0 = B * 16;
            float s = 0.f, sq = 0.f;
#pragma unroll
            for (int r = 0; r < 16; r++) {
                float v = z[(r0 + r) * K + k];
                s += v; sq += v * v;
            }
            g_pS[B * K + k] = s;
            g_pQ[B * K + k] = sq;
        }
    } else {
        int base = (B - 128) * 256 + tid;
        for (int i = base; i < NMAX * K; i += 8 * 256) g_T[i] = 0.f;
        for (int i = base; i < N; i += 8 * 256) g_S[i] = 0.f;
        if (B == 135 && tid == 0) g_acc = 0.f;
    }
    grid_bar(0);

    // ======================= P1: standardize + moments + row norms =========
    if (B < 128) {
        float* shr = reinterpret_cast<float*>(s_buf);   // [4][16]
        const int k = tid;   // only tid < 128 active for compute
        if (tid < 128) {
            float s = 0.f, sq = 0.f;
#pragma unroll 8
            for (int b = 0; b < 128; b++) {
                s  += g_pS[b * K + k];
                sq += g_pQ[b * K + k];
            }
            const float mean = s / (float)N;
            float var = (sq - s * mean) / (float)(N - 1);
            var = fmaxf(var, 0.f);
            const float rs = 1.f / (sqrtf(var) + 1e-6f);

            const int r0 = B * 16;
            float bx[16], q[16], rh16[16];
#pragma unroll
            for (int r = 0; r < 16; r++) {
                int row = r0 + r;
                float xs = (z[row * K + k] - mean) * rs;
                g_xs[row * K + k] = xs;
                g_u [row * K + k] = xs * SQL2E;
                bx[r] = xs;
                q[r]  = ex2f(NL2E * xs * xs);
                rh16[r] = xs * xs;
            }

            float acc[NMAX];
#pragma unroll
            for (int n = 0; n < NMAX; n++) acc[n] = 0.f;
#pragma unroll
            for (int n = 0; n < NMAX; n++) {
                const float rinv = 1.0f / (float)(n + 1);
#pragma unroll
                for (int r = 0; r < 16; r++) {
                    acc[n] += q[r];
                    q[r] *= bx[r] * rinv;
                }
            }
#pragma unroll
            for (int n = 0; n < NMAX; n++) atomicAdd(&g_T[n * K + k], acc[n]);

#pragma unroll
            for (int o = 16; o; o >>= 1)
#pragma unroll
                for (int r = 0; r < 16; r++)
                    rh16[r] += __shfl_xor_sync(0xffffffffu, rh16[r], o);

            const int w = k >> 5, lane = k & 31;
            if (lane == 0) {
#pragma unroll
                for (int r = 0; r < 16; r++) shr[w * 16 + r] = rh16[r];
            }
        }
        __syncthreads();
        if (tid < 16)
            g_rh[B * 16 + tid] = HL2E * (shr[0 * 16 + tid] + shr[1 * 16 + tid]
                                       + shr[2 * 16 + tid] + shr[3 * 16 + tid]);
    }
    grid_bar(1);

    // ======================= P2: Gram + fused exp + row/col sums ===========
    {
        float (*As)[132]  = reinterpret_cast<float(*)[132]>(s_buf);
        float (*Bs)[132]  = reinterpret_cast<float(*)[132]>(s_buf + 16896);
        float (*colP)[128]= reinterpret_cast<float(*)[128]>(s_buf + 33792);

        const int tx = tid & 15, ty = tid >> 4;

        int rem = B, ti = 0;
        for (int t = 0; t < 16; t++) {
            int L = 16 - t;
            if (rem < L) { ti = t; break; }
            rem -= L;
        }
        const int tj = ti + rem;
        const int i0 = ti * 128, j0 = tj * 128;

        ull acc2[8][4];
#pragma unroll
        for (int m = 0; m < 8; m++)
#pragma unroll
            for (int p = 0; p < 4; p++) acc2[m][p] = splat2(0.f);

#pragma unroll 1
        for (int kc = 0; kc < K; kc += 32) {
            __syncthreads();
#pragma unroll
            for (int r = 0; r < 4; r++) {
                int f = tid + 256 * r;
                int row = f >> 3, kp = (f & 7) * 4;
                float4 va = *(const float4*)&g_u[(i0 + row) * K + kc + kp];
                As[kp + 0][row] = va.x; As[kp + 1][row] = va.y;
                As[kp + 2][row] = va.z; As[kp + 3][row] = va.w;
                float4 vb = *(const float4*)&g_u[(j0 + row) * K + kc + kp];
                Bs[kp + 0][row] = vb.x; Bs[kp + 1][row] = vb.y;
                Bs[kp + 2][row] = vb.z; Bs[kp + 3][row] = vb.w;
            }
            __syncthreads();
#pragma unroll
            for (int kk = 0; kk < 32; kk++) {
                float4 a0 = *(const float4*)&As[kk][ty * 8];
                float4 a1 = *(const float4*)&As[kk][ty * 8 + 4];
                float4 b0 = *(const float4*)&Bs[kk][tx * 8];
                float4 b1 = *(const float4*)&Bs[kk][tx * 8 + 4];
                ull av2[8];
                av2[0] = splat2(a0.x); av2[1] = splat2(a0.y);
                av2[2] = splat2(a0.z); av2[3] = splat2(a0.w);
                av2[4] = splat2(a1.x); av2[5] = splat2(a1.y);
                av2[6] = splat2(a1.z); av2[7] = splat2(a1.w);
                ull bv[4];
                bv[0] = pack2(b0.x, b0.y); bv[1] = pack2(b0.z, b0.w);
                bv[2] = pack2(b1.x, b1.y); bv[3] = pack2(b1.z, b1.w);
#pragma unroll
                for (int m = 0; m < 8; m++)
#pragma unroll
                    for (int p = 0; p < 4; p++)
                        acc2[m][p] = fma2(av2[m], bv[p], acc2[m][p]);
            }
        }

        float rhi[8], rhj[8];
#pragma unroll
        for (int m = 0; m < 8; m++) rhi[m] = g_rh[i0 + ty * 8 + m];
#pragma unroll
        for (int n = 0; n < 8; n++) rhj[n] = g_rh[j0 + tx * 8 + n];

        float rows[8], cols[8];
#pragma unroll
        for (int m = 0; m < 8; m++) rows[m] = 0.f;
#pragma unroll
        for (int n = 0; n < 8; n++) cols[n] = 0.f;
#pragma unroll
        for (int m = 0; m < 8; m++) {
#pragma unroll
            for (int p = 0; p < 4; p++) {
                float glo, ghi;
                unpack2(acc2[m][p], glo, ghi);
                float e0 = ex2f(glo - rhi[m] - rhj[2 * p + 0]);
                float e1 = ex2f(ghi - rhi[m] - rhj[2 * p + 1]);
                rows[m] += e0 + e1;
                cols[2 * p + 0] += e0;
                cols[2 * p + 1] += e1;
            }
        }

#pragma unroll
        for (int o = 8; o; o >>= 1)
#pragma unroll
            for (int m = 0; m < 8; m++)
                rows[m] += __shfl_xor_sync(0xffffffffu, rows[m], o);
        if (tx == 0) {
#pragma unroll
            for (int m = 0; m < 8; m++)
                atomicAdd(&g_S[i0 + ty * 8 + m], rows[m]);
        }

#pragma unroll
        for (int n = 0; n < 8; n++) colP[ty][tx * 8 + n] = cols[n];
        __syncthreads();
        if (ti != tj && tid < 128) {
            float ssum = 0.f;
#pragma unroll
            for (int t = 0; t < 16; t++) ssum += colP[t][tid];
            atomicAdd(&g_S[j0 + tid], ssum);
        }
    }
    grid_bar(2);

    // ======================= P3: combine + reduce ===========================
    if (B < 128) {
        float* T_sh = reinterpret_cast<float*>(s_buf);                 // 20 KB
        float* part = reinterpret_cast<float*>(s_buf + NMAX * K * 4);  // [8][8]
        float* vv   = part + 64;                                       // [16]

        const int k = tid & 127;
        const int g = tid >> 7;
        const int i0 = B * 16;
        const int r0 = i0 + g * 8;

        float a[8];
#pragma unroll
        for (int r = 0; r < 8; r++) a[r] = g_xs[(r0 + r) * K + k];

#pragma unroll
        for (int r = 0; r < 5; r++)
            reinterpret_cast<float4*>(T_sh)[tid + 256 * r] =
                reinterpret_cast<const float4*>(g_T)[tid + 256 * r];
        __syncthreads();

        float S[8];
        {
            float t = T_sh[(NMAX - 1) * K + k];
#pragma unroll
            for (int r = 0; r < 8; r++) S[r] = t;
        }
#pragma unroll
        for (int n = NMAX - 2; n >= 0; n--) {
            float t = T_sh[n * K + k];
#pragma unroll
            for (int r = 0; r < 8; r++) S[r] = fmaf(S[r], a[r], t);
        }

        float val[8];
#pragma unroll
        for (int r = 0; r < 8; r++)
            val[r] = lnf(S[r]) - 0.5f * a[r] * a[r];

#pragma unroll
        for (int o = 16; o; o >>= 1)
#pragma unroll
            for (int r = 0; r < 8; r++)
                val[r] += __shfl_xor_sync(0xffffffffu, val[r], o);

        const int ww = tid >> 5, lane = tid & 31;
        if (lane == 0) {
#pragma unroll
            for (int r = 0; r < 8; r++) part[ww * 8 + r] = val[r];
        }
        __syncthreads();
        if (tid < 16) {
            int gg = tid >> 3, rr = tid & 7;
            float tot = part[(gg * 4 + 0) * 8 + rr] + part[(gg * 4 + 1) * 8 + rr]
                      + part[(gg * 4 + 2) * 8 + rr] + part[(gg * 4 + 3) * 8 + rr];
            vv[tid] = logf(g_S[i0 + gg * 8 + rr]) - tot;
        }
        __syncthreads();

        if (tid == 0) {
            float bsum = 0.f;
#pragma unroll
            for (int r = 0; r < 16; r++) bsum += vv[r];
            atomicAdd(&g_acc, bsum);
        }
    }

    // final arrival: last block writes the scalar
    __threadfence();
    __syncthreads();
    if (tid == 0) {
        unsigned ticket = atomicAdd(&g_bar[3], 1u);
        if (ticket % NB == (unsigned)(NB - 1)) {
            __threadfence();
            float total = atomicAdd(&g_acc, 0.f);
            out[0] = total / (float)N + (float)(K - 1) * logf((float)N);
        }
    }
}

// ---------------------------------------------------------------------------
extern "C" void kernel_launch(void* const* d_in, const int* in_sizes, int n_in,
                              void* d_out, int out_size) {
    (void)in_sizes; (void)n_in; (void)out_size;
    const float* z = (const float*)d_in[0];
    float* out = (float*)d_out;

    fused_kernel<<<NB, 256>>>(z, out);
}